// round 5
// baseline (speedup 1.0000x reference)
#include <cuda_runtime.h>

// ChamferDistance: x,y = [16, 4096, 3] fp32 -> scalar
// d = x2 + y2 - 2 x.y ; per-pair t = y2_j - 2 x.y_j ; add x2_i after min.
// R5: PPT=8 (4 LDS.128 feed 32 distances -> L1tex pipe off the critical path,
//     which R4 showed at 55%), 128 blocks = 1 per SM (no wave imbalance).

#define NB      16
#define NPTS    4096
#define SPLITS  4
#define QPB     (NPTS / SPLITS)   // 1024 query points per block
#define THREADS 128
#define PPT     (QPB / THREADS)   // 8 query points per thread
#define NBLOCKS (NB * 2 * SPLITS) // 128

__device__ float g_partial[NBLOCKS];
__device__ unsigned int g_ticket;   // zero-init; reset by last block each run

typedef unsigned long long ull;

__device__ __forceinline__ ull pack2(float a, float b) {
    ull r; asm("mov.b64 %0, {%1, %2};" : "=l"(r) : "f"(a), "f"(b)); return r;
}
__device__ __forceinline__ ull fma2(ull a, ull b, ull c) {
    ull d; asm("fma.rn.f32x2 %0, %1, %2, %3;" : "=l"(d) : "l"(a), "l"(b), "l"(c)); return d;
}
__device__ __forceinline__ void unpack2(ull v, float& lo, float& hi) {
    asm("mov.b64 {%0, %1}, %2;" : "=f"(lo), "=f"(hi) : "l"(v));
}

__global__ __launch_bounds__(THREADS) void chamfer_kernel(
    const float* __restrict__ x, const float* __restrict__ y,
    float* __restrict__ out)
{
    extern __shared__ float smem[];
    float* __restrict__ sx = smem;               // [NPTS]
    float* __restrict__ sy = smem + NPTS;        // [NPTS]
    float* __restrict__ sz = smem + 2 * NPTS;    // [NPTS]
    float* __restrict__ sw = smem + 3 * NPTS;    // [NPTS]  |p|^2

    const int dir = blockIdx.y;       // 0: query=x, db=y ; 1: query=y, db=x
    const int b   = blockIdx.z;
    const float* __restrict__ q  = (dir ? y : x) + (size_t)b * NPTS * 3;
    const float* __restrict__ db = (dir ? x : y) + (size_t)b * NPTS * 3;

    // Cooperative SoA load of db side + precomputed |p|^2.
    for (int j = threadIdx.x; j < NPTS; j += THREADS) {
        float a = db[3 * j + 0];
        float c = db[3 * j + 1];
        float d = db[3 * j + 2];
        sx[j] = a; sy[j] = c; sz[j] = d;
        sw[j] = fmaf(a, a, fmaf(c, c, d * d));
    }
    __syncthreads();

    // Per-thread query points: packed duplicated coefficients {-2q, -2q}.
    ull n0[PPT], n1[PPT], n2[PPT];
    float q2s = 0.0f;
    float m0[PPT], m1[PPT];
    const int qbase = blockIdx.x * QPB + threadIdx.x * PPT;
#pragma unroll
    for (int p = 0; p < PPT; p++) {
        float a = q[3 * (qbase + p) + 0];
        float c = q[3 * (qbase + p) + 1];
        float d = q[3 * (qbase + p) + 2];
        n0[p] = pack2(-2.0f * a, -2.0f * a);
        n1[p] = pack2(-2.0f * c, -2.0f * c);
        n2[p] = pack2(-2.0f * d, -2.0f * d);
        q2s += fmaf(a, a, fmaf(c, c, d * d));   // sum of |q|^2, added at end
        m0[p] = 3.402823466e+38f;
        m1[p] = 3.402823466e+38f;
    }

    // Hot loop per 4 db points per thread: 4x LDS.128 + 6*PPT FFMA2 + 4*PPT FMNMX.
    // 16 independent min-chains (PPT=8 x 2 packed halves) give the ILP needed
    // to saturate the FMA pipe from a single warp per SMSP.
#pragma unroll 2
    for (int j = 0; j < NPTS; j += 4) {
        const ulonglong2 X = *(const ulonglong2*)(sx + j);
        const ulonglong2 Y = *(const ulonglong2*)(sy + j);
        const ulonglong2 Z = *(const ulonglong2*)(sz + j);
        const ulonglong2 W = *(const ulonglong2*)(sw + j);
#pragma unroll
        for (int p = 0; p < PPT; p++) {
            ull ta = fma2(n0[p], X.x, W.x);
            ta = fma2(n1[p], Y.x, ta);
            ta = fma2(n2[p], Z.x, ta);
            ull tb = fma2(n0[p], X.y, W.y);
            tb = fma2(n1[p], Y.y, tb);
            tb = fma2(n2[p], Z.y, tb);
            float a0, a1, b0, b1;
            unpack2(ta, a0, a1);
            unpack2(tb, b0, b1);
            m0[p] = fminf(m0[p], a0);
            m1[p] = fminf(m1[p], a1);
            m0[p] = fminf(m0[p], b0);
            m1[p] = fminf(m1[p], b1);
        }
    }

    // Per-thread sum of NN sq-dists (+ sum |q|^2).
    float s = q2s;
#pragma unroll
    for (int p = 0; p < PPT; p++) s += fminf(m0[p], m1[p]);

    // Warp reduce (fixed shuffle order -> deterministic)
#pragma unroll
    for (int o = 16; o > 0; o >>= 1) s += __shfl_down_sync(0xFFFFFFFFu, s, o);

    __shared__ float red[THREADS / 32];
    __shared__ bool amlast;
    if ((threadIdx.x & 31) == 0) red[threadIdx.x >> 5] = s;
    __syncthreads();
    if (threadIdx.x == 0) {
        float t = 0.0f;
#pragma unroll
        for (int w = 0; w < THREADS / 32; w++) t += red[w];
        const int lin = blockIdx.x + SPLITS * (blockIdx.y + 2 * blockIdx.z);
        g_partial[lin] = t;
        __threadfence();
        unsigned int old = atomicAdd(&g_ticket, 1u);
        amlast = (old == NBLOCKS - 1);
    }
    __syncthreads();

    // Last block reduces all 128 partials in fixed order (deterministic).
    if (amlast) {
        float v = g_partial[threadIdx.x];   // THREADS == NBLOCKS == 128
#pragma unroll
        for (int o = 16; o > 0; o >>= 1) v += __shfl_down_sync(0xFFFFFFFFu, v, o);
        if ((threadIdx.x & 31) == 0) red[threadIdx.x >> 5] = v;
        __syncthreads();
        if (threadIdx.x == 0) {
            float t = 0.0f;
#pragma unroll
            for (int w = 0; w < THREADS / 32; w++) t += red[w];
            out[0] = t * (1.0f / ((float)NB * (float)NPTS));
            g_ticket = 0;   // reset for next graph replay
        }
    }
}

extern "C" void kernel_launch(void* const* d_in, const int* in_sizes, int n_in,
                              void* d_out, int out_size)
{
    const float* x = (const float*)d_in[0];
    const float* y = (const float*)d_in[1];
    float* out = (float*)d_out;

    const int smem = 4 * NPTS * sizeof(float);  // 64 KB SoA
    cudaFuncSetAttribute(chamfer_kernel,
                         cudaFuncAttributeMaxDynamicSharedMemorySize, smem);

    dim3 grid(SPLITS, 2, NB);
    chamfer_kernel<<<grid, THREADS, smem>>>(x, y, out);
}

// round 6
// speedup vs baseline: 1.0979x; 1.0979x over previous
#include <cuda_runtime.h>

// ChamferDistance: x,y = [16, 4096, 3] fp32 -> scalar
// d = x2 + y2 - 2 x.y ; per-pair t = y2_j - 2 x.y_j ; add x2_i after min.
// R6: __launch_bounds__(256,1) unlocks the register budget (R3-R5 were
//     ILP-starved at 64-72 regs -> serialized fma2 chains, issue ~40%).
//     128 blocks x 256 thr = 1 block/SM, 2 warps/SMSP, PPT=4.

#define NB      16
#define NPTS    4096
#define SPLITS  4
#define QPB     (NPTS / SPLITS)   // 1024 query points per block
#define THREADS 256
#define PPT     (QPB / THREADS)   // 4 query points per thread
#define NBLOCKS (NB * 2 * SPLITS) // 128

__device__ float g_partial[NBLOCKS];
__device__ unsigned int g_ticket;   // zero-init; reset by last block each run

typedef unsigned long long ull;

__device__ __forceinline__ ull pack2(float a, float b) {
    ull r; asm("mov.b64 %0, {%1, %2};" : "=l"(r) : "f"(a), "f"(b)); return r;
}
__device__ __forceinline__ ull fma2(ull a, ull b, ull c) {
    ull d; asm("fma.rn.f32x2 %0, %1, %2, %3;" : "=l"(d) : "l"(a), "l"(b), "l"(c)); return d;
}
__device__ __forceinline__ void unpack2(ull v, float& lo, float& hi) {
    asm("mov.b64 {%0, %1}, %2;" : "=f"(lo), "=f"(hi) : "l"(v));
}

__global__ __launch_bounds__(THREADS, 1) void chamfer_kernel(
    const float* __restrict__ x, const float* __restrict__ y,
    float* __restrict__ out)
{
    extern __shared__ float smem[];
    float* __restrict__ sx = smem;               // [NPTS]
    float* __restrict__ sy = smem + NPTS;        // [NPTS]
    float* __restrict__ sz = smem + 2 * NPTS;    // [NPTS]
    float* __restrict__ sw = smem + 3 * NPTS;    // [NPTS]  |p|^2

    const int dir = blockIdx.y;       // 0: query=x, db=y ; 1: query=y, db=x
    const int b   = blockIdx.z;
    const float* __restrict__ q  = (dir ? y : x) + (size_t)b * NPTS * 3;
    const float* __restrict__ db = (dir ? x : y) + (size_t)b * NPTS * 3;

    // Cooperative SoA load of db side + precomputed |p|^2.
    for (int j = threadIdx.x; j < NPTS; j += THREADS) {
        float a = db[3 * j + 0];
        float c = db[3 * j + 1];
        float d = db[3 * j + 2];
        sx[j] = a; sy[j] = c; sz[j] = d;
        sw[j] = fmaf(a, a, fmaf(c, c, d * d));
    }
    __syncthreads();

    // Per-thread query points: packed duplicated coefficients {-2q, -2q}.
    ull n0[PPT], n1[PPT], n2[PPT];
    float q2s = 0.0f;
    float m0[PPT], m1[PPT];
    const int qbase = blockIdx.x * QPB + threadIdx.x * PPT;
#pragma unroll
    for (int p = 0; p < PPT; p++) {
        float a = q[3 * (qbase + p) + 0];
        float c = q[3 * (qbase + p) + 1];
        float d = q[3 * (qbase + p) + 2];
        n0[p] = pack2(-2.0f * a, -2.0f * a);
        n1[p] = pack2(-2.0f * c, -2.0f * c);
        n2[p] = pack2(-2.0f * d, -2.0f * d);
        q2s += fmaf(a, a, fmaf(c, c, d * d));   // sum of |q|^2, added at end
        m0[p] = 3.402823466e+38f;
        m1[p] = 3.402823466e+38f;
    }

    // Hot loop per 4 db points per thread:
    //   4x LDS.128 (two pre-packed f32x2 operands each) + 24 FFMA2 + 16 FMNMX.
    //   8 independent min-chains; with the register budget unlocked, ptxas can
    //   keep all chains in flight and front-batch the loads.
#pragma unroll 2
    for (int j = 0; j < NPTS; j += 4) {
        const ulonglong2 X = *(const ulonglong2*)(sx + j);
        const ulonglong2 Y = *(const ulonglong2*)(sy + j);
        const ulonglong2 Z = *(const ulonglong2*)(sz + j);
        const ulonglong2 W = *(const ulonglong2*)(sw + j);
#pragma unroll
        for (int p = 0; p < PPT; p++) {
            ull ta = fma2(n0[p], X.x, W.x);
            ta = fma2(n1[p], Y.x, ta);
            ta = fma2(n2[p], Z.x, ta);
            ull tb = fma2(n0[p], X.y, W.y);
            tb = fma2(n1[p], Y.y, tb);
            tb = fma2(n2[p], Z.y, tb);
            float a0, a1, b0, b1;
            unpack2(ta, a0, a1);
            unpack2(tb, b0, b1);
            m0[p] = fminf(m0[p], a0);
            m1[p] = fminf(m1[p], a1);
            m0[p] = fminf(m0[p], b0);
            m1[p] = fminf(m1[p], b1);
        }
    }

    // Per-thread sum of NN sq-dists (+ sum |q|^2).
    float s = q2s;
#pragma unroll
    for (int p = 0; p < PPT; p++) s += fminf(m0[p], m1[p]);

    // Warp reduce (fixed shuffle order -> deterministic)
#pragma unroll
    for (int o = 16; o > 0; o >>= 1) s += __shfl_down_sync(0xFFFFFFFFu, s, o);

    __shared__ float red[THREADS / 32];
    __shared__ bool amlast;
    if ((threadIdx.x & 31) == 0) red[threadIdx.x >> 5] = s;
    __syncthreads();
    if (threadIdx.x == 0) {
        float t = 0.0f;
#pragma unroll
        for (int w = 0; w < THREADS / 32; w++) t += red[w];
        const int lin = blockIdx.x + SPLITS * (blockIdx.y + 2 * blockIdx.z);
        g_partial[lin] = t;
        __threadfence();
        unsigned int old = atomicAdd(&g_ticket, 1u);
        amlast = (old == NBLOCKS - 1);
    }
    __syncthreads();

    // Last block: reduce all 128 partials in fixed order (deterministic).
    if (amlast) {
        float v = (threadIdx.x < NBLOCKS) ? g_partial[threadIdx.x] : 0.0f;
#pragma unroll
        for (int o = 16; o > 0; o >>= 1) v += __shfl_down_sync(0xFFFFFFFFu, v, o);
        if ((threadIdx.x & 31) == 0) red[threadIdx.x >> 5] = v;
        __syncthreads();
        if (threadIdx.x == 0) {
            float t = 0.0f;
#pragma unroll
            for (int w = 0; w < THREADS / 32; w++) t += red[w];
            out[0] = t * (1.0f / ((float)NB * (float)NPTS));
            g_ticket = 0;   // reset for next graph replay
        }
    }
}

extern "C" void kernel_launch(void* const* d_in, const int* in_sizes, int n_in,
                              void* d_out, int out_size)
{
    const float* x = (const float*)d_in[0];
    const float* y = (const float*)d_in[1];
    float* out = (float*)d_out;

    const int smem = 4 * NPTS * sizeof(float);  // 64 KB SoA
    cudaFuncSetAttribute(chamfer_kernel,
                         cudaFuncAttributeMaxDynamicSharedMemorySize, smem);

    dim3 grid(SPLITS, 2, NB);
    chamfer_kernel<<<grid, THREADS, smem>>>(x, y, out);
}